// round 4
// baseline (speedup 1.0000x reference)
#include <cuda_runtime.h>
#include <cstdint>
#include <cstddef>

// Problem constants
#define K_B   64
#define K_T   512
#define K_D   512
#define K_U   512
#define K_G3  1536
#define K_K   1024          // fused K (x-half + h-half)
#define N_CTA 128
#define N_THR 256

// ---------------- device scratch (no allocations allowed) ----------------
__device__ float g_WA[3 * K_U * K_K];   // layer0 weights, [gate][unit][k], k<512 -> W0, else U0
__device__ float g_WB[3 * K_U * K_K];   // layer1 weights, k<512 -> W1, else U1
__device__ float g_h0[2 * K_B * K_U];   // double-buffered h0 state
__device__ float g_h1[2 * K_B * K_U];   // double-buffered h1 state
__device__ float g_h0n[K_B * K_U];      // unmasked h0n (layer-1 input)
__device__ unsigned g_bar_count;
__device__ unsigned g_bar_release;

// ---------------- init (reset state every graph replay) ----------------
__global__ void gru_init() {
    int i = blockIdx.x * blockDim.x + threadIdx.x;
    if (i < 2 * K_B * K_U) { g_h0[i] = 0.f; g_h1[i] = 0.f; }
    if (i < K_B * K_U)     { g_h0n[i] = 0.f; }
    if (i == 0) { g_bar_count = 0u; g_bar_release = 0u; }
}

// ---------------- weight pack: [k][3U] -> [gate][unit][k] ----------------
__global__ void gru_pack_weights(const float* __restrict__ W0, const float* __restrict__ U0,
                                 const float* __restrict__ W1, const float* __restrict__ U1) {
    int idx = blockIdx.x * blockDim.x + threadIdx.x;
    if (idx >= 3 * K_U * K_K) return;
    int k = idx & (K_K - 1);
    int u = (idx >> 10) & (K_U - 1);
    int g = idx >> 19;
    int col = g * K_U + u;
    g_WA[idx] = (k < K_D) ? W0[(size_t)k * K_G3 + col] : U0[(size_t)(k - K_D) * K_G3 + col];
    g_WB[idx] = (k < K_U) ? W1[(size_t)k * K_G3 + col] : U1[(size_t)(k - K_U) * K_G3 + col];
}

// ---------------- software grid barrier (all 128 CTAs resident) ----------------
__device__ __forceinline__ void grid_barrier(unsigned target) {
    __syncthreads();
    if (threadIdx.x == 0) {
        __threadfence();
        if (atomicAdd(&g_bar_count, 1u) == (unsigned)gridDim.x - 1u) {
            atomicExch(&g_bar_count, 0u);
            __threadfence();
            atomicExch(&g_bar_release, target);
        } else {
            while (*(volatile unsigned*)&g_bar_release < target) { }
            __threadfence();
        }
    }
    __syncthreads();
}

__device__ __forceinline__ float sigmoid_f(float x) { return 1.f / (1.f + __expf(-x)); }

// one GRU-cell dot-product group: z,r over K=1024; third gate split (x-part, h-part)
__device__ __forceinline__ void cell_dots(const float4* __restrict__ v0,   // x-like vec (512)
                                          const float4* __restrict__ v1,   // h-like vec (512)
                                          const float4* __restrict__ wz,
                                          const float4* __restrict__ wr,
                                          const float4* __restrict__ wh,
                                          float& oz, float& orr, float& o3x, float& o3h) {
    float sz = 0.f, sr = 0.f, sx = 0.f, sh = 0.f;
#pragma unroll 4
    for (int kk = 0; kk < K_D / 4; ++kk) {
        float4 v = v0[kk];
        float4 a = wz[kk]; float4 b = wr[kk]; float4 c = wh[kk];
        sz = fmaf(v.x, a.x, sz); sz = fmaf(v.y, a.y, sz); sz = fmaf(v.z, a.z, sz); sz = fmaf(v.w, a.w, sz);
        sr = fmaf(v.x, b.x, sr); sr = fmaf(v.y, b.y, sr); sr = fmaf(v.z, b.z, sr); sr = fmaf(v.w, b.w, sr);
        sx = fmaf(v.x, c.x, sx); sx = fmaf(v.y, c.y, sx); sx = fmaf(v.z, c.z, sx); sx = fmaf(v.w, c.w, sx);
    }
#pragma unroll 4
    for (int kk = 0; kk < K_U / 4; ++kk) {
        float4 v = v1[kk];
        float4 a = wz[K_D / 4 + kk]; float4 b = wr[K_D / 4 + kk]; float4 c = wh[K_D / 4 + kk];
        sz = fmaf(v.x, a.x, sz); sz = fmaf(v.y, a.y, sz); sz = fmaf(v.z, a.z, sz); sz = fmaf(v.w, a.w, sz);
        sr = fmaf(v.x, b.x, sr); sr = fmaf(v.y, b.y, sr); sr = fmaf(v.z, b.z, sr); sr = fmaf(v.w, b.w, sr);
        sh = fmaf(v.x, c.x, sh); sh = fmaf(v.y, c.y, sh); sh = fmaf(v.z, c.z, sh); sh = fmaf(v.w, c.w, sh);
    }
    oz = sz; orr = sr; o3x = sx; o3h = sh;
}

// ---------------- persistent GRU kernel ----------------
__global__ void __launch_bounds__(N_THR, 1) gru_main(
    const float* __restrict__ x, const int* __restrict__ mask,
    const float* __restrict__ b0, const float* __restrict__ b1,
    float* __restrict__ out) {

    const int tid  = threadIdx.x;
    const int b    = tid >> 2;                       // 0..63
    const int u    = (blockIdx.x << 2) | (tid & 3);  // 0..511
    const int hidx = b * K_U + u;

    const float4* wAz = reinterpret_cast<const float4*>(g_WA + (size_t)(0 * K_U + u) * K_K);
    const float4* wAr = reinterpret_cast<const float4*>(g_WA + (size_t)(1 * K_U + u) * K_K);
    const float4* wAh = reinterpret_cast<const float4*>(g_WA + (size_t)(2 * K_U + u) * K_K);
    const float4* wBz = reinterpret_cast<const float4*>(g_WB + (size_t)(0 * K_U + u) * K_K);
    const float4* wBr = reinterpret_cast<const float4*>(g_WB + (size_t)(1 * K_U + u) * K_K);
    const float4* wBh = reinterpret_cast<const float4*>(g_WB + (size_t)(2 * K_U + u) * K_K);

    // biases: z/r combine b[0]+b[1]; candidate keeps input/hidden parts separate
    const float bAz = b0[u]            + b0[K_G3 + u];
    const float bAr = b0[K_U + u]      + b0[K_G3 + K_U + u];
    const float bAi = b0[2 * K_U + u];
    const float bAh = b0[K_G3 + 2 * K_U + u];
    const float bBz = b1[u]            + b1[K_G3 + u];
    const float bBr = b1[K_U + u]      + b1[K_G3 + K_U + u];
    const float bBi = b1[2 * K_U + u];
    const float bBh = b1[K_G3 + 2 * K_U + u];

    float h0v = 0.f;   // carried (masked) h0 for this (b,u)
    float h1v = 0.f;   // carried (masked) h1 for this (b,u)
    float prev = 0.f;  // previous output value for this (b,u)
    unsigned bar = 0;

    for (int t = 0; t < K_T; ++t) {
        const int p = t & 1;
        // mask robust to int32 OR float32 encoding: both are 4-byte, nonzero bits iff true
        const bool m = mask[(size_t)b * K_T + t] != 0;

        // -------- phase A: layer 0  ([x_t, h0] @ [W0;U0]) --------
        {
            const float4* xv  = reinterpret_cast<const float4*>(x + ((size_t)b * K_T + t) * K_D);
            const float4* h0r = reinterpret_cast<const float4*>(g_h0 + (size_t)p * K_B * K_U + (size_t)b * K_U);
            float sz, sr, sx, sh;
            cell_dots(xv, h0r, wAz, wAr, wAh, sz, sr, sx, sh);
            float z    = sigmoid_f(sz + bAz);
            float r    = sigmoid_f(sr + bAr);
            float cand = tanhf(sx + bAi + r * (sh + bAh));
            float h0n  = z * h0v + (1.f - z) * cand;
            g_h0n[hidx] = h0n;                 // unmasked: feeds layer 1
            h0v = m ? h0n : h0v;               // masked carry
            g_h0[(size_t)(p ^ 1) * K_B * K_U + hidx] = h0v;
        }
        grid_barrier(++bar);

        // -------- phase B: layer 1  ([h0n, h1] @ [W1;U1]) --------
        {
            const float4* h0nv = reinterpret_cast<const float4*>(g_h0n + (size_t)b * K_U);
            const float4* h1r  = reinterpret_cast<const float4*>(g_h1 + (size_t)p * K_B * K_U + (size_t)b * K_U);
            float sz, sr, sx, sh;
            cell_dots(h0nv, h1r, wBz, wBr, wBh, sz, sr, sx, sh);
            float z    = sigmoid_f(sz + bBz);
            float r    = sigmoid_f(sr + bBr);
            float cand = tanhf(sx + bBi + r * (sh + bBh));
            float h1n  = z * h1v + (1.f - z) * cand;
            h1v = m ? h1n : h1v;
            g_h1[(size_t)(p ^ 1) * K_B * K_U + hidx] = h1v;
            prev = m ? h1n : prev;
            out[((size_t)b * K_T + t) * K_U + u] = prev;
        }
        grid_barrier(++bar);
    }

    // finals: (output, h0f, h1f) packed in d_out
    out[(size_t)K_B * K_T * K_U + hidx] = h0v;
    out[(size_t)K_B * K_T * K_U + K_B * K_U + hidx] = h1v;
}

// ---------------- launch (graph-capturable: kernels only) ----------------
extern "C" void kernel_launch(void* const* d_in, const int* in_sizes, int n_in,
                              void* d_out, int out_size) {
    (void)in_sizes; (void)n_in; (void)out_size;
    const float* x    = (const float*)d_in[0];
    const int*   mask = (const int*)d_in[1];    // bool mask materialized as int32/float32
    const float* W0   = (const float*)d_in[2];
    const float* U0   = (const float*)d_in[3];
    const float* b0   = (const float*)d_in[4];
    const float* W1   = (const float*)d_in[5];
    const float* U1   = (const float*)d_in[6];
    const float* b1   = (const float*)d_in[7];
    float*       out  = (float*)d_out;

    gru_init<<<(2 * K_B * K_U + 255) / 256, 256>>>();
    gru_pack_weights<<<(3 * K_U * K_K + 255) / 256, 256>>>(W0, U0, W1, U1);
    gru_main<<<N_CTA, N_THR>>>(x, mask, b0, b1, out);
}

// round 5
// speedup vs baseline: 2.5406x; 2.5406x over previous
#include <cuda_runtime.h>
#include <cstdint>
#include <cstddef>

// Problem constants
#define K_B   64
#define K_T   512
#define K_D   512
#define K_U   512
#define K_G3  1536
#define N_CTA 128
#define N_THR 256
#define SMEM_BYTES (2 * 3 * 4 * 1024 * 4)   // 96 KB: [layer][gate][4u][1024k] f32

// ---------------- device scratch ----------------
__device__ float g_WA[3 * K_U * 1024];        // layer0 packed [gate][u][k] (k<512:W0, else U0)
__device__ float g_WB[3 * K_U * 1024];        // layer1 packed [gate][u][k] (k<512:W1, else U1)
__device__ float g_xT[(size_t)K_T * 128 * K_B * 4]; // x transposed: [t][kb][b][ki] (64 MB)
__device__ float g_h0[2 * 128 * K_B * 4];     // h0 blocked [p][kb][b][ki]
__device__ float g_h1[2 * 128 * K_B * 4];     // h1 blocked
__device__ float g_h0n[128 * K_B * 4];        // unmasked h0n blocked
__device__ unsigned g_bar_count;
__device__ unsigned g_bar_release;

// ---------------- init (reset state every replay) ----------------
__global__ void gru_init() {
    int i = blockIdx.x * blockDim.x + threadIdx.x;
    if (i < 2 * 128 * K_B * 4) { g_h0[i] = 0.f; g_h1[i] = 0.f; }
    if (i < 128 * K_B * 4)     { g_h0n[i] = 0.f; }
    if (i == 0) { g_bar_count = 0u; g_bar_release = 0u; }
}

// ---------------- weight pack: [k][3U] -> [gate][u][k] ----------------
__global__ void gru_pack_weights(const float* __restrict__ W0, const float* __restrict__ U0,
                                 const float* __restrict__ W1, const float* __restrict__ U1) {
    int idx = blockIdx.x * blockDim.x + threadIdx.x;
    if (idx >= 3 * K_U * 1024) return;
    int k = idx & 1023;
    int u = (idx >> 10) & (K_U - 1);
    int g = idx >> 19;
    int col = g * K_U + u;
    g_WA[idx] = (k < K_D) ? W0[(size_t)k * K_G3 + col] : U0[(size_t)(k - K_D) * K_G3 + col];
    g_WB[idx] = (k < K_U) ? W1[(size_t)k * K_G3 + col] : U1[(size_t)(k - K_U) * K_G3 + col];
}

// ---------------- x transpose: [b][t][d] -> [t][d/4][b][4] ----------------
__global__ void gru_transpose_x(const float* __restrict__ x) {
    size_t idx = (size_t)blockIdx.x * blockDim.x + threadIdx.x;  // over 512*128*64 float4
    if (idx >= (size_t)K_T * 128 * K_B) return;
    int b  = idx & 63;
    int kb = (int)(idx >> 6) & 127;
    int t  = (int)(idx >> 13);
    float4 v = reinterpret_cast<const float4*>(x)[((size_t)b * K_T + t) * 128 + kb];
    reinterpret_cast<float4*>(g_xT)[idx] = v;
}

// ---------------- software grid barrier ----------------
__device__ __forceinline__ void grid_barrier(unsigned target) {
    __syncthreads();
    if (threadIdx.x == 0) {
        __threadfence();
        if (atomicAdd(&g_bar_count, 1u) == (unsigned)gridDim.x - 1u) {
            atomicExch(&g_bar_count, 0u);
            __threadfence();
            atomicExch(&g_bar_release, target);
        } else {
            while (*(volatile unsigned*)&g_bar_release < target) { }
            __threadfence();
        }
    }
    __syncthreads();
}

__device__ __forceinline__ float sigmoid_f(float x) { return 1.f / (1.f + __expf(-x)); }

// dots over K=1024 (two 512 halves, blocked [kb][b] float4); weights broadcast from SMEM
__device__ __forceinline__ void dots4(const float4* __restrict__ v0,  // pre-offset by b; stride 64
                                      const float4* __restrict__ v1,
                                      const float4* __restrict__ w,   // sW4 + layer*3072 + uu*256
                                      float& oz, float& orr, float& o3x, float& o3h) {
    float sz = 0.f, sr = 0.f, sx = 0.f, sh = 0.f;
#pragma unroll 4
    for (int kb = 0; kb < 128; ++kb) {
        float4 v = v0[(size_t)kb * 64];
        float4 a = w[kb]; float4 bq = w[1024 + kb]; float4 c = w[2048 + kb];
        sz = fmaf(v.x, a.x, sz);  sz = fmaf(v.y, a.y, sz);  sz = fmaf(v.z, a.z, sz);  sz = fmaf(v.w, a.w, sz);
        sr = fmaf(v.x, bq.x, sr); sr = fmaf(v.y, bq.y, sr); sr = fmaf(v.z, bq.z, sr); sr = fmaf(v.w, bq.w, sr);
        sx = fmaf(v.x, c.x, sx);  sx = fmaf(v.y, c.y, sx);  sx = fmaf(v.z, c.z, sx);  sx = fmaf(v.w, c.w, sx);
    }
#pragma unroll 4
    for (int kb = 0; kb < 128; ++kb) {
        float4 v = v1[(size_t)kb * 64];
        float4 a = w[128 + kb]; float4 bq = w[1024 + 128 + kb]; float4 c = w[2048 + 128 + kb];
        sz = fmaf(v.x, a.x, sz);  sz = fmaf(v.y, a.y, sz);  sz = fmaf(v.z, a.z, sz);  sz = fmaf(v.w, a.w, sz);
        sr = fmaf(v.x, bq.x, sr); sr = fmaf(v.y, bq.y, sr); sr = fmaf(v.z, bq.z, sr); sr = fmaf(v.w, bq.w, sr);
        sh = fmaf(v.x, c.x, sh);  sh = fmaf(v.y, c.y, sh);  sh = fmaf(v.z, c.z, sh);  sh = fmaf(v.w, c.w, sh);
    }
    oz = sz; orr = sr; o3x = sx; o3h = sh;
}
// NOTE on weight SMEM layout used above: per (layer,uu) base w holds gate-z k-blocks
// [0..255] where [0..127] = x-half, [128..255] = h-half; gates r,h at +1024, +2048.

// ---------------- persistent GRU kernel ----------------
__global__ void __launch_bounds__(N_THR, 1) gru_main(
    const float* __restrict__ x, const int* __restrict__ mask,
    const float* __restrict__ b0, const float* __restrict__ b1,
    float* __restrict__ out) {

    extern __shared__ float sW[];                 // [layer][gate][uu][1024]
    float4* sW4 = reinterpret_cast<float4*>(sW);

    const int tid   = threadIdx.x;
    const int lane  = tid & 31;
    const int bhalf = tid >> 7;                   // 0..1
    const int uu    = (tid >> 5) & 3;             // 0..3
    const int b     = lane | (bhalf << 5);        // 0..63
    const int u0g   = blockIdx.x << 2;
    const int u     = u0g + uu;

    // ---- stage weights for this CTA's 4 u into SMEM (coalesced, once) ----
    for (int layer = 0; layer < 2; ++layer) {
        const float4* src = reinterpret_cast<const float4*>(layer ? g_WB : g_WA);
#pragma unroll
        for (int g = 0; g < 3; ++g)
#pragma unroll
            for (int w = 0; w < 4; ++w)
                sW4[((layer * 3 + g) * 4 + w) * 256 + tid] = src[(g * K_U + u0g + w) * 256 + tid];
    }
    __syncthreads();

    const float4* wA = sW4 + uu * 256;            // layer 0 base for this u
    const float4* wB = sW4 + 3072 + uu * 256;     // layer 1 base

    // biases: z/r combine input+hidden parts; candidate keeps them split
    const float bAz = b0[u]           + b0[K_G3 + u];
    const float bAr = b0[K_U + u]     + b0[K_G3 + K_U + u];
    const float bAi = b0[2 * K_U + u];
    const float bAh = b0[K_G3 + 2 * K_U + u];
    const float bBz = b1[u]           + b1[K_G3 + u];
    const float bBr = b1[K_U + u]     + b1[K_G3 + K_U + u];
    const float bBi = b1[2 * K_U + u];
    const float bBh = b1[K_G3 + 2 * K_U + u];

    const int hw = (u >> 2) * 256 + b * 4 + (u & 3);   // blocked [kb][b][ki] write index

    float h0v = 0.f, h1v = 0.f, prev = 0.f;
    unsigned bar = 0;

    for (int t = 0; t < K_T; ++t) {
        const int p = t & 1;
        const bool m = mask[(size_t)b * K_T + t] != 0;

        // ---- phase A: layer 0, [x_t ; h0] ----
        {
            const float4* xv  = reinterpret_cast<const float4*>(g_xT) + (size_t)t * 128 * 64 + b;
            const float4* h0r = reinterpret_cast<const float4*>(g_h0) + (size_t)p * 8192 + b;
            float sz, sr, sx, sh;
            dots4(xv, h0r, wA, sz, sr, sx, sh);
            float z    = sigmoid_f(sz + bAz);
            float r    = sigmoid_f(sr + bAr);
            float cand = tanhf(sx + bAi + r * (sh + bAh));
            float h0n  = z * h0v + (1.f - z) * cand;
            g_h0n[hw] = h0n;                            // unmasked: feeds layer 1
            h0v = m ? h0n : h0v;
            g_h0[(size_t)(p ^ 1) * 32768 + hw] = h0v;
        }
        grid_barrier(++bar);

        // ---- phase B: layer 1, [h0n ; h1] ----
        {
            const float4* h0nv = reinterpret_cast<const float4*>(g_h0n) + b;
            const float4* h1r  = reinterpret_cast<const float4*>(g_h1) + (size_t)p * 8192 + b;
            float sz, sr, sx, sh;
            dots4(h0nv, h1r, wB, sz, sr, sx, sh);
            float z    = sigmoid_f(sz + bBz);
            float r    = sigmoid_f(sr + bBr);
            float cand = tanhf(sx + bBi + r * (sh + bBh));
            float h1n  = z * h1v + (1.f - z) * cand;
            h1v = m ? h1n : h1v;
            g_h1[(size_t)(p ^ 1) * 32768 + hw] = h1v;
            prev = m ? h1n : prev;
            out[((size_t)b * K_T + t) * K_U + u] = prev;
        }
        grid_barrier(++bar);
    }

    // finals: (output, h0f, h1f) packed in d_out, [b][u] row-major
    const size_t fin = (size_t)K_B * K_T * K_U;
    out[fin + (size_t)b * K_U + u] = h0v;
    out[fin + (size_t)K_B * K_U + (size_t)b * K_U + u] = h1v;
}

// ---------------- launch ----------------
extern "C" void kernel_launch(void* const* d_in, const int* in_sizes, int n_in,
                              void* d_out, int out_size) {
    (void)in_sizes; (void)n_in; (void)out_size;
    const float* x    = (const float*)d_in[0];
    const int*   mask = (const int*)d_in[1];
    const float* W0   = (const float*)d_in[2];
    const float* U0   = (const float*)d_in[3];
    const float* b0   = (const float*)d_in[4];
    const float* W1   = (const float*)d_in[5];
    const float* U1   = (const float*)d_in[6];
    const float* b1   = (const float*)d_in[7];
    float*       out  = (float*)d_out;

    cudaFuncSetAttribute(gru_main, cudaFuncAttributeMaxDynamicSharedMemorySize, SMEM_BYTES);

    gru_init<<<(2 * 128 * K_B * 4 + 255) / 256, 256>>>();
    gru_pack_weights<<<(3 * K_U * 1024 + 255) / 256, 256>>>(W0, U0, W1, U1);
    {
        size_t n4 = (size_t)K_T * 128 * K_B;
        gru_transpose_x<<<(unsigned)((n4 + 255) / 256), 256>>>(x);
    }
    gru_main<<<N_CTA, N_THR, SMEM_BYTES>>>(x, mask, b0, b1, out);
}

// round 6
// speedup vs baseline: 4.2520x; 1.6736x over previous
#include <cuda_runtime.h>
#include <cstdint>
#include <cstddef>

// Problem constants
#define K_B   64
#define K_T   512
#define K_U   512
#define K_G3  1536
#define N_CTA 128
#define N_THR 256

// SMEM layout (bytes)
#define W_BYTES   98304          // 2 layers * 3 gates * 4 u * 1024 k * 4B
#define X_OFF     98304
#define X_BYTES   131072         // 64 b * 512 k * 4B  (one timestep of x, blocked [kb][b] float4)
#define MBAR_OFF  229376
#define SMEM_TOTAL 229392

// ---------------- device scratch ----------------
__device__ float g_WA[3 * K_U * 1024];            // layer0 [gate][u][k]
__device__ float g_WB[3 * K_U * 1024];            // layer1
__device__ float g_xT[(size_t)K_T * K_B * K_U];   // x blocked [t][kb][b][ki]
__device__ float g_h0[2 * K_B * K_U];             // double-buffered, blocked [kb][b][ki]
__device__ float g_h1[2 * K_B * K_U];
__device__ float g_h0n[K_B * K_U];
__device__ unsigned g_bar_count;
__device__ unsigned g_bar_release;

// ---------------- init ----------------
__global__ void gru_init() {
    int i = blockIdx.x * blockDim.x + threadIdx.x;
    if (i < 2 * K_B * K_U) { g_h0[i] = 0.f; g_h1[i] = 0.f; }
    if (i < K_B * K_U)     { g_h0n[i] = 0.f; }
    if (i == 0) { g_bar_count = 0u; g_bar_release = 0u; }
}

// ---------------- weight pack: [k][3U] -> [gate][u][k] ----------------
__global__ void gru_pack_weights(const float* __restrict__ W0, const float* __restrict__ U0,
                                 const float* __restrict__ W1, const float* __restrict__ U1) {
    int idx = blockIdx.x * blockDim.x + threadIdx.x;
    if (idx >= 3 * K_U * 1024) return;
    int k = idx & 1023;
    int u = (idx >> 10) & (K_U - 1);
    int g = idx >> 19;
    int col = g * K_U + u;
    g_WA[idx] = (k < 512) ? W0[(size_t)k * K_G3 + col] : U0[(size_t)(k - 512) * K_G3 + col];
    g_WB[idx] = (k < 512) ? W1[(size_t)k * K_G3 + col] : U1[(size_t)(k - 512) * K_G3 + col];
}

// ---------------- x transpose: [b][t][d] -> [t][d/4][b][4] ----------------
__global__ void gru_transpose_x(const float* __restrict__ x) {
    size_t idx = (size_t)blockIdx.x * blockDim.x + threadIdx.x;
    if (idx >= (size_t)K_T * 128 * K_B) return;
    int b  = idx & 63;
    int kb = (int)(idx >> 6) & 127;
    int t  = (int)(idx >> 13);
    float4 v = reinterpret_cast<const float4*>(x)[((size_t)b * K_T + t) * 128 + kb];
    reinterpret_cast<float4*>(g_xT)[idx] = v;
}

// ---------------- grid barrier ----------------
__device__ __forceinline__ void grid_barrier(unsigned target) {
    __syncthreads();
    if (threadIdx.x == 0) {
        __threadfence();
        if (atomicAdd(&g_bar_count, 1u) == (unsigned)gridDim.x - 1u) {
            atomicExch(&g_bar_count, 0u);
            __threadfence();
            atomicExch(&g_bar_release, target);
        } else {
            while (*(volatile unsigned*)&g_bar_release < target) { }
            __threadfence();
        }
    }
    __syncthreads();
}

__device__ __forceinline__ float sigmoid_f(float x) { return 1.f / (1.f + __expf(-x)); }

// ---------------- f32x2 / load primitives ----------------
__device__ __forceinline__ void lds2(uint32_t a, uint64_t& x, uint64_t& y) {
    asm volatile("ld.shared.v2.u64 {%0,%1},[%2];" : "=l"(x), "=l"(y) : "r"(a));
}
__device__ __forceinline__ void ldg2(const void* p, uint64_t& x, uint64_t& y) {
    asm volatile("ld.global.cg.v2.u64 {%0,%1},[%2];" : "=l"(x), "=l"(y) : "l"(p));
}
__device__ __forceinline__ void fma2(uint64_t& d, uint64_t a, uint64_t b) {
    asm volatile("fma.rn.f32x2 %0,%1,%2,%0;" : "+l"(d) : "l"(a), "l"(b));
}
__device__ __forceinline__ float redu(uint64_t a, uint64_t b) {
    float x0, x1, y0, y1;
    asm volatile("mov.b64 {%0,%1},%2;" : "=f"(x0), "=f"(x1) : "l"(a));
    asm volatile("mov.b64 {%0,%1},%2;" : "=f"(y0), "=f"(y1) : "l"(b));
    return (x0 + x1) + (y0 + y1);
}

#define MWAIT(mbar, ph) do {                                                             \
    asm volatile("{\n\t.reg .pred P1;\n\t"                                               \
                 "WL_%=:\n\t"                                                            \
                 "mbarrier.try_wait.parity.acquire.cta.shared::cta.b64 P1,[%0],%1;\n\t" \
                 "@P1 bra.uni WD_%=;\n\t"                                                \
                 "bra.uni WL_%=;\n\t"                                                    \
                 "WD_%=:\n\t}"                                                           \
                 :: "r"(mbar), "r"(ph) : "memory");                                      \
} while (0)

// 512-k half-dot: v from SMEM (x buffer). wz = smem addr of gate-z weights for this (layer,u,half)
__device__ __forceinline__ void half_s(uint32_t vbase, uint32_t wz,
                                       uint64_t& z0, uint64_t& z1, uint64_t& r0, uint64_t& r1,
                                       uint64_t& c0, uint64_t& c1) {
#pragma unroll
    for (int g = 0; g < 16; ++g) {
        uint64_t v[16];
#pragma unroll
        for (int j = 0; j < 8; ++j)
            lds2(vbase + (unsigned)(g * 8 + j) * 1024u, v[2 * j], v[2 * j + 1]);
#pragma unroll
        for (int j = 0; j < 8; ++j) {
            uint32_t wo = wz + (unsigned)(g * 8 + j) * 16u;
            uint64_t a, bq;
            lds2(wo,           a, bq); fma2(z0, v[2 * j], a); fma2(z1, v[2 * j + 1], bq);
            lds2(wo + 16384u,  a, bq); fma2(r0, v[2 * j], a); fma2(r1, v[2 * j + 1], bq);
            lds2(wo + 32768u,  a, bq); fma2(c0, v[2 * j], a); fma2(c1, v[2 * j + 1], bq);
        }
    }
}

// 512-k half-dot: v from global (L2-direct .cg), vbase pre-offset by b*16
__device__ __forceinline__ void half_g(const char* vbase, uint32_t wz,
                                       uint64_t& z0, uint64_t& z1, uint64_t& r0, uint64_t& r1,
                                       uint64_t& c0, uint64_t& c1) {
#pragma unroll
    for (int g = 0; g < 16; ++g) {
        uint64_t v[16];
#pragma unroll
        for (int j = 0; j < 8; ++j)
            ldg2(vbase + (size_t)(g * 8 + j) * 1024, v[2 * j], v[2 * j + 1]);
#pragma unroll
        for (int j = 0; j < 8; ++j) {
            uint32_t wo = wz + (unsigned)(g * 8 + j) * 16u;
            uint64_t a, bq;
            lds2(wo,           a, bq); fma2(z0, v[2 * j], a); fma2(z1, v[2 * j + 1], bq);
            lds2(wo + 16384u,  a, bq); fma2(r0, v[2 * j], a); fma2(r1, v[2 * j + 1], bq);
            lds2(wo + 32768u,  a, bq); fma2(c0, v[2 * j], a); fma2(c1, v[2 * j + 1], bq);
        }
    }
}

// ---------------- persistent GRU kernel ----------------
__global__ void __launch_bounds__(N_THR, 1) gru_main(
    const int* __restrict__ mask,
    const float* __restrict__ b0, const float* __restrict__ b1,
    float* __restrict__ out) {

    extern __shared__ char smem[];
    const uint32_t sbase = (uint32_t)__cvta_generic_to_shared(smem);
    float4* sW4 = reinterpret_cast<float4*>(smem);

    const int tid   = threadIdx.x;
    const int lane  = tid & 31;
    const int bhalf = tid >> 7;
    const int uu    = (tid >> 5) & 3;
    const int b     = lane | (bhalf << 5);
    const int u0g   = blockIdx.x << 2;
    const int u     = u0g + uu;

    // ---- stage weights into SMEM ----
    for (int layer = 0; layer < 2; ++layer) {
        const float4* src = reinterpret_cast<const float4*>(layer ? g_WB : g_WA);
#pragma unroll
        for (int g = 0; g < 3; ++g)
#pragma unroll
            for (int w = 0; w < 4; ++w)
                sW4[((layer * 3 + g) * 4 + w) * 256 + tid] = src[(g * K_U + u0g + w) * 256 + tid];
    }
    const uint32_t mbar = sbase + MBAR_OFF;
    if (tid == 0)
        asm volatile("mbarrier.init.shared.b64 [%0], 1;" :: "r"(mbar));
    __syncthreads();

    // ---- prefetch x tile for t=0 ----
    if (tid == 0) {
        asm volatile("fence.proxy.async.shared::cta;");
        asm volatile("mbarrier.arrive.expect_tx.shared.b64 _,[%0],%1;" :: "r"(mbar), "r"(X_BYTES));
        asm volatile("cp.async.bulk.shared::cta.global.mbarrier::complete_tx::bytes [%0],[%1],%2,[%3];"
                     :: "r"(sbase + X_OFF), "l"((const void*)g_xT), "r"(X_BYTES), "r"(mbar) : "memory");
    }

    // weight bases: ((layer*3 + gate)*4 + uu) * 4096 bytes; gate stride 16384; h-half +2048
    const uint32_t wA = sbase + (uint32_t)uu * 4096u;
    const uint32_t wB = sbase + 49152u + (uint32_t)uu * 4096u;

    const float bAz = b0[u]           + b0[K_G3 + u];
    const float bAr = b0[K_U + u]     + b0[K_G3 + K_U + u];
    const float bAi = b0[2 * K_U + u];
    const float bAh = b0[K_G3 + 2 * K_U + u];
    const float bBz = b1[u]           + b1[K_G3 + u];
    const float bBr = b1[K_U + u]     + b1[K_G3 + K_U + u];
    const float bBi = b1[2 * K_U + u];
    const float bBh = b1[K_G3 + 2 * K_U + u];

    const int hw = (u >> 2) * 256 + b * 4 + (u & 3);   // blocked [kb][b][ki] float index

    float h0v = 0.f, h1v = 0.f, prev = 0.f;
    unsigned bar = 0;

    for (int t = 0; t < K_T; ++t) {
        const int p = t & 1;
        const bool m = mask[(size_t)b * K_T + t] != 0;

        // ---- phase A: layer 0, [x_t(smem) ; h0(global)] ----
        MWAIT(mbar, (unsigned)(t & 1));
        {
            uint64_t z0 = 0, z1 = 0, r0 = 0, r1 = 0, cx0 = 0, cx1 = 0, ch0 = 0, ch1 = 0;
            half_s(sbase + X_OFF + (unsigned)b * 16u, wA, z0, z1, r0, r1, cx0, cx1);
            half_g((const char*)g_h0 + (size_t)p * 131072 + (size_t)b * 16, wA + 2048u,
                   z0, z1, r0, r1, ch0, ch1);
            float z    = sigmoid_f(redu(z0, z1) + bAz);
            float r    = sigmoid_f(redu(r0, r1) + bAr);
            float cand = tanhf(redu(cx0, cx1) + bAi + r * (redu(ch0, ch1) + bAh));
            float h0n  = z * h0v + (1.f - z) * cand;
            g_h0n[hw] = h0n;
            h0v = m ? h0n : h0v;
            g_h0[(size_t)(p ^ 1) * 32768 + hw] = h0v;
        }
        grid_barrier(++bar);

        // ---- prefetch x(t+1) (overlaps phase B compute) ----
        if (tid == 0 && t + 1 < K_T) {
            asm volatile("fence.proxy.async.shared::cta;");
            asm volatile("mbarrier.arrive.expect_tx.shared.b64 _,[%0],%1;" :: "r"(mbar), "r"(X_BYTES));
            asm volatile("cp.async.bulk.shared::cta.global.mbarrier::complete_tx::bytes [%0],[%1],%2,[%3];"
                         :: "r"(sbase + X_OFF), "l"((const void*)(g_xT + (size_t)(t + 1) * 32768)),
                            "r"(X_BYTES), "r"(mbar) : "memory");
        }

        // ---- phase B: layer 1, [h0n ; h1] ----
        {
            uint64_t z0 = 0, z1 = 0, r0 = 0, r1 = 0, cx0 = 0, cx1 = 0, ch0 = 0, ch1 = 0;
            half_g((const char*)g_h0n + (size_t)b * 16, wB, z0, z1, r0, r1, cx0, cx1);
            half_g((const char*)g_h1 + (size_t)p * 131072 + (size_t)b * 16, wB + 2048u,
                   z0, z1, r0, r1, ch0, ch1);
            float z    = sigmoid_f(redu(z0, z1) + bBz);
            float r    = sigmoid_f(redu(r0, r1) + bBr);
            float cand = tanhf(redu(cx0, cx1) + bBi + r * (redu(ch0, ch1) + bBh));
            float h1n  = z * h1v + (1.f - z) * cand;
            h1v = m ? h1n : h1v;
            g_h1[(size_t)(p ^ 1) * 32768 + hw] = h1v;
            prev = m ? h1n : prev;
            out[((size_t)b * K_T + t) * K_U + u] = prev;
        }
        grid_barrier(++bar);
    }

    // finals: (output, h0f, h1f) packed in d_out, [b][u]
    const size_t fin = (size_t)K_B * K_T * K_U;
    out[fin + (size_t)b * K_U + u] = h0v;
    out[fin + (size_t)K_B * K_U + (size_t)b * K_U + u] = h1v;
}

// ---------------- launch ----------------
extern "C" void kernel_launch(void* const* d_in, const int* in_sizes, int n_in,
                              void* d_out, int out_size) {
    (void)in_sizes; (void)n_in; (void)out_size;
    const float* x    = (const float*)d_in[0];
    const int*   mask = (const int*)d_in[1];
    const float* W0   = (const float*)d_in[2];
    const float* U0   = (const float*)d_in[3];
    const float* b0   = (const float*)d_in[4];
    const float* W1   = (const float*)d_in[5];
    const float* U1   = (const float*)d_in[6];
    const float* b1   = (const float*)d_in[7];
    float*       out  = (float*)d_out;

    cudaFuncSetAttribute(gru_main, cudaFuncAttributeMaxDynamicSharedMemorySize, SMEM_TOTAL);

    gru_init<<<(2 * K_B * K_U + 255) / 256, 256>>>();
    gru_pack_weights<<<(3 * K_U * 1024 + 255) / 256, 256>>>(W0, U0, W1, U1);
    {
        size_t n4 = (size_t)K_T * 128 * K_B;
        gru_transpose_x<<<(unsigned)((n4 + 255) / 256), 256>>>(x);
    }
    gru_main<<<N_CTA, N_THR, SMEM_TOTAL>>>(mask, b0, b1, out);
}

// round 7
// speedup vs baseline: 4.6756x; 1.0996x over previous
#include <cuda_runtime.h>
#include <cstdint>
#include <cstddef>

// Problem constants
#define K_B   64
#define K_T   512
#define K_U   512
#define K_G3  1536
#define N_CTA 128
#define N_THR 256

// SMEM layout (bytes): weights 96KB + x tile 128KB + mbar
#define X_OFF     98304
#define X_BYTES   131072
#define MBAR_OFF  229376
#define SMEM_TOTAL 229392

// ---------------- device scratch ----------------
__device__ float g_WA[3 * K_U * 1024];            // layer0 [gate][u][k]
__device__ float g_WB[3 * K_U * 1024];            // layer1
__device__ float g_xT[(size_t)K_T * K_B * K_U];   // x blocked [t][kb][b][ki]
__device__ float g_h0[2 * K_B * K_U];             // double-buffered blocked [kb][b][ki]
__device__ float g_h1[2 * K_B * K_U];
__device__ float g_h0n[K_B * K_U];
__device__ float g_red[(size_t)N_CTA * 64 * 8 * 16]; // partials: [cta][b][kh][16]
__device__ unsigned g_bar_count;
__device__ unsigned g_bar_release;

// ---------------- init ----------------
__global__ void gru_init() {
    int i = blockIdx.x * blockDim.x + threadIdx.x;
    if (i < 2 * K_B * K_U) { g_h0[i] = 0.f; g_h1[i] = 0.f; }
    if (i < K_B * K_U)     { g_h0n[i] = 0.f; }
    if (i == 0) { g_bar_count = 0u; g_bar_release = 0u; }
}

// ---------------- weight pack: [k][3U] -> [gate][u][k] ----------------
__global__ void gru_pack_weights(const float* __restrict__ W0, const float* __restrict__ U0,
                                 const float* __restrict__ W1, const float* __restrict__ U1) {
    int idx = blockIdx.x * blockDim.x + threadIdx.x;
    if (idx >= 3 * K_U * 1024) return;
    int k = idx & 1023;
    int u = (idx >> 10) & (K_U - 1);
    int g = idx >> 19;
    int col = g * K_U + u;
    g_WA[idx] = (k < 512) ? W0[(size_t)k * K_G3 + col] : U0[(size_t)(k - 512) * K_G3 + col];
    g_WB[idx] = (k < 512) ? W1[(size_t)k * K_G3 + col] : U1[(size_t)(k - 512) * K_G3 + col];
}

// ---------------- x transpose: [b][t][d] -> [t][d/4][b][4] ----------------
__global__ void gru_transpose_x(const float* __restrict__ x) {
    size_t idx = (size_t)blockIdx.x * blockDim.x + threadIdx.x;
    if (idx >= (size_t)K_T * 128 * K_B) return;
    int b  = idx & 63;
    int kb = (int)(idx >> 6) & 127;
    int t  = (int)(idx >> 13);
    float4 v = reinterpret_cast<const float4*>(x)[((size_t)b * K_T + t) * 128 + kb];
    reinterpret_cast<float4*>(g_xT)[idx] = v;
}

// ---------------- grid barrier ----------------
__device__ __forceinline__ void grid_barrier(unsigned target) {
    __syncthreads();
    if (threadIdx.x == 0) {
        __threadfence();
        if (atomicAdd(&g_bar_count, 1u) == (unsigned)gridDim.x - 1u) {
            atomicExch(&g_bar_count, 0u);
            __threadfence();
            atomicExch(&g_bar_release, target);
        } else {
            while (*(volatile unsigned*)&g_bar_release < target) { }
            __threadfence();
        }
    }
    __syncthreads();
}

__device__ __forceinline__ float sigmoid_f(float x) { return 1.f / (1.f + __expf(-x)); }

// ---------------- primitives ----------------
__device__ __forceinline__ void lds2(uint32_t a, uint64_t& x, uint64_t& y) {
    asm volatile("ld.shared.v2.u64 {%0,%1},[%2];" : "=l"(x), "=l"(y) : "r"(a));
}
__device__ __forceinline__ void ldg2(const void* p, uint64_t& x, uint64_t& y) {
    asm volatile("ld.global.cg.v2.u64 {%0,%1},[%2];" : "=l"(x), "=l"(y) : "l"(p));
}
__device__ __forceinline__ void fma2(uint64_t& d, uint64_t a, uint64_t b) {
    asm volatile("fma.rn.f32x2 %0,%1,%2,%0;" : "+l"(d) : "l"(a), "l"(b));
}
__device__ __forceinline__ float redu1(uint64_t a) {
    float x0, x1;
    asm volatile("mov.b64 {%0,%1},%2;" : "=f"(x0), "=f"(x1) : "l"(a));
    return x0 + x1;
}

#define MWAIT(mbar, ph) do {                                                             \
    asm volatile("{\n\t.reg .pred P1;\n\t"                                               \
                 "WL_%=:\n\t"                                                            \
                 "mbarrier.try_wait.parity.acquire.cta.shared::cta.b64 P1,[%0],%1;\n\t" \
                 "@P1 bra.uni WD_%=;\n\t"                                                \
                 "bra.uni WL_%=;\n\t"                                                    \
                 "WD_%=:\n\t}"                                                           \
                 :: "r"(mbar), "r"(ph) : "memory");                                      \
} while (0)

// FMA body for one 4-k chunk, 2 b's x 4 u x 3 gates
#define CHUNK_FMA(C)                                                                     \
    _Pragma("unroll")                                                                    \
    for (int g = 0; g < 3; ++g) {                                                        \
        _Pragma("unroll")                                                                \
        for (int u = 0; u < 4; ++u) {                                                    \
            uint64_t wl, wh;                                                             \
            lds2(wb + (unsigned)(g * 16384 + u * 4096 + (C) * 16), wl, wh);              \
            const int j = g * 4 + u;                                                     \
            fma2(acc[j], v0l, wl);      fma2(acc[j], v0h, wh);                           \
            fma2(acc[12 + j], v1l, wl); fma2(acc[12 + j], v1h, wh);                      \
        }                                                                                \
    }

// 128-k quarter-dot, v from SMEM (x). vb pre-offset by lane*16; wb = weight base (incl. kh offset)
__device__ __forceinline__ void dotq_s(uint32_t vb, uint32_t wb, uint64_t* acc) {
#pragma unroll
    for (int c = 0; c < 32; ++c) {
        uint64_t v0l, v0h, v1l, v1h;
        lds2(vb + (unsigned)c * 1024u, v0l, v0h);
        lds2(vb + (unsigned)c * 1024u + 512u, v1l, v1h);
        CHUNK_FMA(c)
    }
}

// 128-k quarter-dot, v from global (.cg), with distance-1 prefetch
__device__ __forceinline__ void dotq_g(const char* vp, uint32_t wb, uint64_t* acc) {
    uint64_t p0l, p0h, p1l, p1h;
    ldg2(vp, p0l, p0h);
    ldg2(vp + 512, p1l, p1h);
#pragma unroll
    for (int c = 0; c < 32; ++c) {
        uint64_t v0l = p0l, v0h = p0h, v1l = p1l, v1h = p1h;
        if (c < 31) {
            ldg2(vp + (size_t)(c + 1) * 1024, p0l, p0h);
            ldg2(vp + (size_t)(c + 1) * 1024 + 512, p1l, p1h);
        }
        CHUNK_FMA(c)
    }
}

// write 24 partial scalars (2 b's x 12) to g_red
__device__ __forceinline__ void write_partials(int cta, int lane, int kh, const uint64_t* acc) {
#pragma unroll
    for (int bp = 0; bp < 2; ++bp) {
        int b = lane + bp * 32;
        float4* dst = reinterpret_cast<float4*>(g_red) + ((size_t)(cta * 64 + b) * 8 + kh) * 4;
#pragma unroll
        for (int q = 0; q < 3; ++q) {
            float4 v;
            v.x = redu1(acc[bp * 12 + q * 4 + 0]);
            v.y = redu1(acc[bp * 12 + q * 4 + 1]);
            v.z = redu1(acc[bp * 12 + q * 4 + 2]);
            v.w = redu1(acc[bp * 12 + q * 4 + 3]);
            dst[q] = v;
        }
    }
}

// gather partials for one b: slo = sum kh 0..3 (input half), shi = sum kh 4..7 (hidden half)
__device__ __forceinline__ void gather(int cta, int b, float* slo, float* shi) {
    const float4* base = reinterpret_cast<const float4*>(g_red) + (size_t)(cta * 64 + b) * 32;
    float4 a[6];
#pragma unroll
    for (int i = 0; i < 6; ++i) a[i] = make_float4(0.f, 0.f, 0.f, 0.f);
#pragma unroll
    for (int kh = 0; kh < 8; ++kh) {
#pragma unroll
        for (int q = 0; q < 3; ++q) {
            float4 v = __ldcg(base + kh * 4 + q);
            int s = (kh < 4) ? q : 3 + q;
            a[s].x += v.x; a[s].y += v.y; a[s].z += v.z; a[s].w += v.w;
        }
    }
#pragma unroll
    for (int q = 0; q < 3; ++q) {
        slo[q * 4 + 0] = a[q].x;     slo[q * 4 + 1] = a[q].y;
        slo[q * 4 + 2] = a[q].z;     slo[q * 4 + 3] = a[q].w;
        shi[q * 4 + 0] = a[3 + q].x; shi[q * 4 + 1] = a[3 + q].y;
        shi[q * 4 + 2] = a[3 + q].z; shi[q * 4 + 3] = a[3 + q].w;
    }
}

// ---------------- persistent GRU kernel ----------------
__global__ void __launch_bounds__(N_THR, 1) gru_main(
    const int* __restrict__ mask,
    const float* __restrict__ b0, const float* __restrict__ b1,
    float* __restrict__ out) {

    extern __shared__ char smem[];
    const uint32_t sbase = (uint32_t)__cvta_generic_to_shared(smem);
    float4* sW4 = reinterpret_cast<float4*>(smem);

    const int tid  = threadIdx.x;
    const int lane = tid & 31;
    const int kh   = tid >> 5;              // 0..7: K-eighth
    const int cta  = blockIdx.x;
    const int u0g  = cta << 2;

    // ---- stage weights into SMEM ----
    for (int layer = 0; layer < 2; ++layer) {
        const float4* src = reinterpret_cast<const float4*>(layer ? g_WB : g_WA);
#pragma unroll
        for (int g = 0; g < 3; ++g)
#pragma unroll
            for (int w = 0; w < 4; ++w)
                sW4[((layer * 3 + g) * 4 + w) * 256 + tid] = src[(g * K_U + u0g + w) * 256 + tid];
    }
    const uint32_t mbar = sbase + MBAR_OFF;
    if (tid == 0)
        asm volatile("mbarrier.init.shared.b64 [%0], 1;" :: "r"(mbar));
    __syncthreads();

    // ---- prefetch x tile for t=0 ----
    if (tid == 0) {
        asm volatile("fence.proxy.async.shared::cta;");
        asm volatile("mbarrier.arrive.expect_tx.shared.b64 _,[%0],%1;" :: "r"(mbar), "r"(X_BYTES));
        asm volatile("cp.async.bulk.shared::cta.global.mbarrier::complete_tx::bytes [%0],[%1],%2,[%3];"
                     :: "r"(sbase + X_OFF), "l"((const void*)g_xT), "r"(X_BYTES), "r"(mbar) : "memory");
    }

    // weight bases for this warp's K-eighth (k-local offset: (kh % 4)*128 k = *512 bytes)
    const uint32_t wA = sbase + (uint32_t)(kh & 3) * 512u + ((kh & 4) ? 2048u : 0u);
    const uint32_t wB = wA + 49152u;

    // finisher (warps 0,1) precomputed biases over 4 u
    const bool fin = (kh < 2);
    const int  fb  = kh * 32 + lane;        // finisher's b
    float bz0[4], br0[4], bi0[4], bh0[4], bz1[4], br1[4], bi1[4], bh1[4];
    if (fin) {
#pragma unroll
        for (int u = 0; u < 4; ++u) {
            int uu = u0g + u;
            bz0[u] = b0[uu] + b0[K_G3 + uu];
            br0[u] = b0[K_U + uu] + b0[K_G3 + K_U + uu];
            bi0[u] = b0[2 * K_U + uu];
            bh0[u] = b0[K_G3 + 2 * K_U + uu];
            bz1[u] = b1[uu] + b1[K_G3 + uu];
            br1[u] = b1[K_U + uu] + b1[K_G3 + K_U + uu];
            bi1[u] = b1[2 * K_U + uu];
            bh1[u] = b1[K_G3 + 2 * K_U + uu];
        }
    }

    float h0v[4] = {0, 0, 0, 0}, h1v[4] = {0, 0, 0, 0}, prev[4] = {0, 0, 0, 0};
    const int f4idx = cta * 64;             // float4 slot base for state writes (kb = cta)
    unsigned bar = 0;

    for (int t = 0; t < K_T; ++t) {
        const int p = t & 1;

        // ======== phase A: layer 0, [x(smem, kh<4) ; h0(global, kh>=4)] ========
        MWAIT(mbar, (unsigned)(t & 1));
        {
            uint64_t acc[24];
#pragma unroll
            for (int i = 0; i < 24; ++i) acc[i] = 0;
            if (kh < 4) {
                dotq_s(sbase + X_OFF + (unsigned)kh * 32768u + (unsigned)lane * 16u, wA, acc);
            } else {
                dotq_g((const char*)g_h0 + (size_t)p * 131072 + (size_t)(kh - 4) * 32768
                       + (size_t)lane * 16, wA, acc);
            }
            write_partials(cta, lane, kh, acc);
        }
        __syncthreads();
        if (fin) {
            float slo[12], shi[12];
            gather(cta, fb, slo, shi);
            const bool m = mask[(size_t)fb * K_T + t] != 0;
            float4 h0n4, h0c4;
#pragma unroll
            for (int u = 0; u < 4; ++u) {
                float z    = sigmoid_f(slo[u] + shi[u] + bz0[u]);
                float r    = sigmoid_f(slo[4 + u] + shi[4 + u] + br0[u]);
                float cand = tanhf(slo[8 + u] + bi0[u] + r * (shi[8 + u] + bh0[u]));
                float h0n  = z * h0v[u] + (1.f - z) * cand;
                h0v[u] = m ? h0n : h0v[u];
                ((float*)&h0n4)[u] = h0n;
                ((float*)&h0c4)[u] = h0v[u];
            }
            reinterpret_cast<float4*>(g_h0n)[f4idx + fb] = h0n4;
            reinterpret_cast<float4*>(g_h0)[(size_t)(p ^ 1) * 8192 + f4idx + fb] = h0c4;
        }
        grid_barrier(++bar);

        // ---- prefetch x(t+1), overlaps phase B ----
        if (tid == 0 && t + 1 < K_T) {
            asm volatile("fence.proxy.async.shared::cta;");
            asm volatile("mbarrier.arrive.expect_tx.shared.b64 _,[%0],%1;" :: "r"(mbar), "r"(X_BYTES));
            asm volatile("cp.async.bulk.shared::cta.global.mbarrier::complete_tx::bytes [%0],[%1],%2,[%3];"
                         :: "r"(sbase + X_OFF), "l"((const void*)(g_xT + (size_t)(t + 1) * 32768)),
                            "r"(X_BYTES), "r"(mbar) : "memory");
        }

        // ======== phase B: layer 1, [h0n(kh<4) ; h1(kh>=4)] ========
        {
            uint64_t acc[24];
#pragma unroll
            for (int i = 0; i < 24; ++i) acc[i] = 0;
            if (kh < 4) {
                dotq_g((const char*)g_h0n + (size_t)kh * 32768 + (size_t)lane * 16, wB, acc);
            } else {
                dotq_g((const char*)g_h1 + (size_t)p * 131072 + (size_t)(kh - 4) * 32768
                       + (size_t)lane * 16, wB, acc);
            }
            write_partials(cta, lane, kh, acc);
        }
        __syncthreads();
        if (fin) {
            float slo[12], shi[12];
            gather(cta, fb, slo, shi);
            const bool m = mask[(size_t)fb * K_T + t] != 0;
            float4 h1c4, out4;
#pragma unroll
            for (int u = 0; u < 4; ++u) {
                float z    = sigmoid_f(slo[u] + shi[u] + bz1[u]);
                float r    = sigmoid_f(slo[4 + u] + shi[4 + u] + br1[u]);
                float cand = tanhf(slo[8 + u] + bi1[u] + r * (shi[8 + u] + bh1[u]));
                float h1n  = z * h1v[u] + (1.f - z) * cand;
                h1v[u]  = m ? h1n : h1v[u];
                prev[u] = m ? h1n : prev[u];
                ((float*)&h1c4)[u] = h1v[u];
                ((float*)&out4)[u] = prev[u];
            }
            reinterpret_cast<float4*>(g_h1)[(size_t)(p ^ 1) * 8192 + f4idx + fb] = h1c4;
            reinterpret_cast<float4*>(out)[((size_t)fb * K_T + t) * 128 + (u0g >> 2)] = out4;
        }
        grid_barrier(++bar);
    }

    // finals: (output, h0f, h1f) in d_out; [b][u] row-major
    if (fin) {
        const size_t fin0 = (size_t)K_B * K_T * 128;   // in float4 units
        float4 a, c;
#pragma unroll
        for (int u = 0; u < 4; ++u) { ((float*)&a)[u] = h0v[u]; ((float*)&c)[u] = h1v[u]; }
        reinterpret_cast<float4*>(out)[fin0 + (size_t)fb * 128 + (u0g >> 2)] = a;
        reinterpret_cast<float4*>(out)[fin0 + 8192 + (size_t)fb * 128 + (u0g >> 2)] = c;
    }
}

// ---------------- launch ----------------
extern "C" void kernel_launch(void* const* d_in, const int* in_sizes, int n_in,
                              void* d_out, int out_size) {
    (void)in_sizes; (void)n_in; (void)out_size;
    const float* x    = (const float*)d_in[0];
    const int*   mask = (const int*)d_in[1];
    const float* W0   = (const float*)d_in[2];
    const float* U0   = (const float*)d_in[3];
    const float* b0   = (const float*)d_in[4];
    const float* W1   = (const float*)d_in[5];
    const float* U1   = (const float*)d_in[6];
    const float* b1   = (const float*)d_in[7];
    float*       out  = (float*)d_out;

    cudaFuncSetAttribute(gru_main, cudaFuncAttributeMaxDynamicSharedMemorySize, SMEM_TOTAL);

    gru_init<<<(2 * K_B * K_U + 255) / 256, 256>>>();
    gru_pack_weights<<<(3 * K_U * 1024 + 255) / 256, 256>>>(W0, U0, W1, U1);
    {
        size_t n4 = (size_t)K_T * 128 * K_B;
        gru_transpose_x<<<(unsigned)((n4 + 255) / 256), 256>>>(x);
    }
    gru_main<<<N_CTA, N_THR, SMEM_TOTAL>>>(mask, b0, b1, out);
}

// round 8
// speedup vs baseline: 6.2739x; 1.3418x over previous
#include <cuda_runtime.h>
#include <cstdint>
#include <cstddef>

// Problem constants
#define K_B   64
#define K_T   512
#define K_U   512
#define K_G3  1536
#define N_CTA 128
#define N_THR 256

// SMEM layout (bytes): weights 96KB + x tile 128KB + mbar
#define X_OFF     98304
#define X_BYTES   131072
#define MBAR_OFF  229376
#define SMEM_TOTAL 229392

// ---------------- device scratch ----------------
__device__ float g_WA[3 * K_U * 1024];            // layer0 [gate][u][k]
__device__ float g_WB[3 * K_U * 1024];            // layer1
__device__ float g_xT[(size_t)K_T * K_B * K_U];   // x blocked [t][kb][b][ki]
__device__ float g_h0[2 * K_B * K_U];             // double-buffered blocked [kb][b][ki]
__device__ float g_h1[2 * K_B * K_U];
__device__ float g_h0n[2 * K_B * K_U];            // double-buffered by t&1
__device__ float g_red[(size_t)N_CTA * 64 * 8 * 16]; // partials: [cta][b][kh][16]
__device__ unsigned g_arrive[N_CTA];
__device__ unsigned g_release;

// ---------------- init (reset per replay) ----------------
__global__ void gru_init() {
    int i = blockIdx.x * blockDim.x + threadIdx.x;
    if (i < 2 * K_B * K_U) { g_h0[i] = 0.f; g_h1[i] = 0.f; g_h0n[i] = 0.f; }
    if (i < N_CTA) g_arrive[i] = 0u;
    if (i == 0)    g_release = 0u;
}

// ---------------- weight pack: [k][3U] -> [gate][u][k] ----------------
__global__ void gru_pack_weights(const float* __restrict__ W0, const float* __restrict__ U0,
                                 const float* __restrict__ W1, const float* __restrict__ U1) {
    int idx = blockIdx.x * blockDim.x + threadIdx.x;
    if (idx >= 3 * K_U * 1024) return;
    int k = idx & 1023;
    int u = (idx >> 10) & (K_U - 1);
    int g = idx >> 19;
    int col = g * K_U + u;
    g_WA[idx] = (k < 512) ? W0[(size_t)k * K_G3 + col] : U0[(size_t)(k - 512) * K_G3 + col];
    g_WB[idx] = (k < 512) ? W1[(size_t)k * K_G3 + col] : U1[(size_t)(k - 512) * K_G3 + col];
}

// ---------------- x transpose: [b][t][d] -> [t][d/4][b][4] ----------------
__global__ void gru_transpose_x(const float* __restrict__ x) {
    size_t idx = (size_t)blockIdx.x * blockDim.x + threadIdx.x;
    if (idx >= (size_t)K_T * 128 * K_B) return;
    int b  = idx & 63;
    int kb = (int)(idx >> 6) & 127;
    int t  = (int)(idx >> 13);
    float4 v = reinterpret_cast<const float4*>(x)[((size_t)b * K_T + t) * 128 + kb];
    reinterpret_cast<float4*>(g_xT)[idx] = v;
}

// ---------------- flag-based grid barrier (1 per step) ----------------
__device__ __forceinline__ void grid_barrier(unsigned step) {
    __syncthreads();
    if (threadIdx.x == 0) {
        __threadfence();
        *(volatile unsigned*)&g_arrive[blockIdx.x] = step;
    }
    if (blockIdx.x == 0) {
        if (threadIdx.x < N_CTA)
            while (*(volatile unsigned*)&g_arrive[threadIdx.x] < step) { }
        __syncthreads();
        if (threadIdx.x == 0) {
            __threadfence();
            *(volatile unsigned*)&g_release = step;
        }
    } else {
        if (threadIdx.x == 0) {
            while (*(volatile unsigned*)&g_release < step) { }
            __threadfence();
        }
    }
    __syncthreads();
}

__device__ __forceinline__ float sigmoid_f(float x) { return 1.f / (1.f + __expf(-x)); }

// ---------------- primitives ----------------
__device__ __forceinline__ void lds2(uint32_t a, uint64_t& x, uint64_t& y) {
    asm volatile("ld.shared.v2.u64 {%0,%1},[%2];" : "=l"(x), "=l"(y) : "r"(a));
}
__device__ __forceinline__ void ldg2(const void* p, uint64_t& x, uint64_t& y) {
    asm volatile("ld.global.cg.v2.u64 {%0,%1},[%2];" : "=l"(x), "=l"(y) : "l"(p));
}
__device__ __forceinline__ void fma2(uint64_t& d, uint64_t a, uint64_t b) {
    asm volatile("fma.rn.f32x2 %0,%1,%2,%0;" : "+l"(d) : "l"(a), "l"(b));
}
__device__ __forceinline__ float redu1(uint64_t a) {
    float x0, x1;
    asm volatile("mov.b64 {%0,%1},%2;" : "=f"(x0), "=f"(x1) : "l"(a));
    return x0 + x1;
}

#define MWAIT(mbar, ph) do {                                                             \
    asm volatile("{\n\t.reg .pred P1;\n\t"                                               \
                 "WL_%=:\n\t"                                                            \
                 "mbarrier.try_wait.parity.acquire.cta.shared::cta.b64 P1,[%0],%1;\n\t" \
                 "@P1 bra.uni WD_%=;\n\t"                                                \
                 "bra.uni WL_%=;\n\t"                                                    \
                 "WD_%=:\n\t}"                                                           \
                 :: "r"(mbar), "r"(ph) : "memory");                                      \
} while (0)

// FMA body for one 4-k chunk: 2 b x 4 u x 3 gates
#define CHUNK_FMA(C)                                                                     \
    _Pragma("unroll")                                                                    \
    for (int g = 0; g < 3; ++g) {                                                        \
        _Pragma("unroll")                                                                \
        for (int u = 0; u < 4; ++u) {                                                    \
            uint64_t wl, wh;                                                             \
            lds2(wb + (unsigned)(g * 16384 + u * 4096 + (C) * 16), wl, wh);              \
            const int j = g * 4 + u;                                                     \
            fma2(acc[j], v0l, wl);      fma2(acc[j], v0h, wh);                           \
            fma2(acc[12 + j], v1l, wl); fma2(acc[12 + j], v1h, wh);                      \
        }                                                                                \
    }

// 128-k quarter-dot, v from SMEM
__device__ __forceinline__ void dotq_s(uint32_t vb, uint32_t wb, uint64_t* acc) {
#pragma unroll
    for (int c = 0; c < 32; ++c) {
        uint64_t v0l, v0h, v1l, v1h;
        lds2(vb + (unsigned)c * 1024u, v0l, v0h);
        lds2(vb + (unsigned)c * 1024u + 512u, v1l, v1h);
        CHUNK_FMA(c)
    }
}

// 128-k quarter-dot, v from global (.cg), group-of-4 double-buffered prefetch
__device__ __forceinline__ void dotq_g(const char* vp, uint32_t wb, uint64_t* acc) {
    uint64_t va[16], vn[16];
#pragma unroll
    for (int j = 0; j < 4; ++j) {
        ldg2(vp + (size_t)j * 1024, va[4 * j], va[4 * j + 1]);
        ldg2(vp + (size_t)j * 1024 + 512, va[4 * j + 2], va[4 * j + 3]);
    }
#pragma unroll
    for (int grp = 0; grp < 8; ++grp) {
        if (grp < 7) {
#pragma unroll
            for (int j = 0; j < 4; ++j) {
                ldg2(vp + (size_t)((grp + 1) * 4 + j) * 1024, vn[4 * j], vn[4 * j + 1]);
                ldg2(vp + (size_t)((grp + 1) * 4 + j) * 1024 + 512, vn[4 * j + 2], vn[4 * j + 3]);
            }
        }
#pragma unroll
        for (int c4 = 0; c4 < 4; ++c4) {
            const int c = grp * 4 + c4;
            uint64_t v0l = va[4 * c4], v0h = va[4 * c4 + 1];
            uint64_t v1l = va[4 * c4 + 2], v1h = va[4 * c4 + 3];
            CHUNK_FMA(c)
        }
#pragma unroll
        for (int j = 0; j < 16; ++j) va[j] = vn[j];
    }
}

// write 24 partial scalars (2 b x 12) to g_red[cta][b][kh][16]
__device__ __forceinline__ void write_partials(int cta, int lane, int kh, const uint64_t* acc) {
#pragma unroll
    for (int bp = 0; bp < 2; ++bp) {
        int b = lane + bp * 32;
        float4* dst = reinterpret_cast<float4*>(g_red) + ((size_t)(cta * 64 + b) * 8 + kh) * 4;
#pragma unroll
        for (int q = 0; q < 3; ++q) {
            float4 v;
            v.x = redu1(acc[bp * 12 + q * 4 + 0]);
            v.y = redu1(acc[bp * 12 + q * 4 + 1]);
            v.z = redu1(acc[bp * 12 + q * 4 + 2]);
            v.w = redu1(acc[bp * 12 + q * 4 + 3]);
            dst[q] = v;
        }
    }
}

// all-thread gather: thread (b = tid>>2, q = tid&3) -> slo/shi[12] via 6 ldcg + shfl
__device__ __forceinline__ void gather2(int cta, int b, int q, float* slo, float* shi) {
    const float4* base = reinterpret_cast<const float4*>(g_red)
                       + (size_t)(cta * 64 + b) * 32 + q * 8;
    float s[12];
#pragma unroll
    for (int i = 0; i < 3; ++i) {
        float4 a = __ldcg(base + i);
        float4 c = __ldcg(base + 4 + i);
        s[i * 4 + 0] = a.x + c.x; s[i * 4 + 1] = a.y + c.y;
        s[i * 4 + 2] = a.z + c.z; s[i * 4 + 3] = a.w + c.w;
    }
#pragma unroll
    for (int i = 0; i < 12; ++i)
        s[i] += __shfl_xor_sync(0xffffffffu, s[i], 1);
    // lanes q<2 hold slo (kh 0..3); q>=2 hold shi (kh 4..7); exchange via xor 2
#pragma unroll
    for (int i = 0; i < 12; ++i) {
        float o = __shfl_xor_sync(0xffffffffu, s[i], 2);
        slo[i] = (q < 2) ? s[i] : o;
        shi[i] = (q < 2) ? o : s[i];
    }
}
__device__ __forceinline__ float pick4(const float* a, int q) {
    float r = (q == 1) ? a[1] : a[0];
    float r2 = (q == 3) ? a[3] : a[2];
    return (q < 2) ? r : r2;
}

// ---------------- persistent GRU kernel ----------------
__global__ void __launch_bounds__(N_THR, 1) gru_main(
    const int* __restrict__ mask,
    const float* __restrict__ b0, const float* __restrict__ b1,
    float* __restrict__ out) {

    extern __shared__ char smem[];
    const uint32_t sbase = (uint32_t)__cvta_generic_to_shared(smem);
    float4* sW4 = reinterpret_cast<float4*>(smem);

    const int tid  = threadIdx.x;
    const int lane = tid & 31;
    const int kh   = tid >> 5;              // dot role: K-eighth
    const int cta  = blockIdx.x;
    const int u0g  = cta << 2;
    const int fb   = tid >> 2;              // finish role: batch
    const int fq   = tid & 3;               // finish role: u within CTA

    // ---- stage weights into SMEM ----
    for (int layer = 0; layer < 2; ++layer) {
        const float4* src = reinterpret_cast<const float4*>(layer ? g_WB : g_WA);
#pragma unroll
        for (int g = 0; g < 3; ++g)
#pragma unroll
            for (int w = 0; w < 4; ++w)
                sW4[((layer * 3 + g) * 4 + w) * 256 + tid] = src[(g * K_U + u0g + w) * 256 + tid];
    }
    const uint32_t mbar = sbase + MBAR_OFF;
    if (tid == 0)
        asm volatile("mbarrier.init.shared.b64 [%0], 1;" :: "r"(mbar));
    __syncthreads();

    // ---- prefetch x tile for t=0 ----
    if (tid == 0) {
        asm volatile("fence.proxy.async.shared::cta;");
        asm volatile("mbarrier.arrive.expect_tx.shared.b64 _,[%0],%1;" :: "r"(mbar), "r"(X_BYTES));
        asm volatile("cp.async.bulk.shared::cta.global.mbarrier::complete_tx::bytes [%0],[%1],%2,[%3];"
                     :: "r"(sbase + X_OFF), "l"((const void*)g_xT), "r"(X_BYTES), "r"(mbar) : "memory");
    }

    // weight bases for this warp's K-eighth
    const uint32_t wA = sbase + (uint32_t)(kh & 3) * 512u + ((kh & 4) ? 2048u : 0u);
    const uint32_t wB = wA + 49152u;

    // per-thread (finish role) biases for u = u0g + fq
    const int uu = u0g + fq;
    const float bAz = b0[uu] + b0[K_G3 + uu];
    const float bAr = b0[K_U + uu] + b0[K_G3 + K_U + uu];
    const float bAi = b0[2 * K_U + uu];
    const float bAh = b0[K_G3 + 2 * K_U + uu];
    const float bBz = b1[uu] + b1[K_G3 + uu];
    const float bBr = b1[K_U + uu] + b1[K_G3 + K_U + uu];
    const float bBi = b1[2 * K_U + uu];
    const float bBh = b1[K_G3 + 2 * K_U + uu];

    const int sidx = cta * 256 + fb * 4 + fq;   // blocked [kb=cta][b][ki] state index
    float h0v = 0.f, h1v = 0.f, prev = 0.f;
    bool m = false;

    for (int t = 0; t < K_T; ++t) {
        const int p = t & 1;

        // ======== phase A: layer 0, [x(smem, kh<4) ; h0(global, kh>=4)] ========
        MWAIT(mbar, (unsigned)p);
        uint64_t acc[24];
#pragma unroll
        for (int i = 0; i < 24; ++i) acc[i] = 0;
        if (kh < 4) {
            dotq_s(sbase + X_OFF + (unsigned)kh * 32768u + (unsigned)lane * 16u, wA, acc);
        } else {
            dotq_g((const char*)g_h0 + (size_t)p * 131072 + (size_t)(kh - 4) * 32768
                   + (size_t)lane * 16, wA, acc);
        }
        __syncthreads();   // x consumed; B(t-1) gather done (red reusable)
        if (tid == 0 && t + 1 < K_T) {
            asm volatile("fence.proxy.async.shared::cta;");
            asm volatile("mbarrier.arrive.expect_tx.shared.b64 _,[%0],%1;" :: "r"(mbar), "r"(X_BYTES));
            asm volatile("cp.async.bulk.shared::cta.global.mbarrier::complete_tx::bytes [%0],[%1],%2,[%3];"
                         :: "r"(sbase + X_OFF), "l"((const void*)(g_xT + (size_t)(t + 1) * 32768)),
                            "r"(X_BYTES), "r"(mbar) : "memory");
        }
        write_partials(cta, lane, kh, acc);
        __syncthreads();
        // ---- A finish (all threads; thread = (fb, fq)) ----
        {
            float slo[12], shi[12];
            gather2(cta, fb, fq, slo, shi);
            m = mask[(size_t)fb * K_T + t] != 0;
            float z    = sigmoid_f(pick4(slo, fq) + pick4(shi, fq) + bAz);
            float r    = sigmoid_f(pick4(slo + 4, fq) + pick4(shi + 4, fq) + bAr);
            float cand = tanhf(pick4(slo + 8, fq) + bAi + r * (pick4(shi + 8, fq) + bAh));
            float h0n  = z * h0v + (1.f - z) * cand;
            h0v = m ? h0n : h0v;
            g_h0n[p * 32768 + sidx] = h0n;
            g_h0[(p ^ 1) * 32768 + sidx] = h0v;
        }
        grid_barrier((unsigned)(t + 1));    // single barrier per step

        // ======== phase B: layer 1, [h0n(kh<4) ; h1(kh>=4)] ========
#pragma unroll
        for (int i = 0; i < 24; ++i) acc[i] = 0;
        if (kh < 4) {
            dotq_g((const char*)g_h0n + (size_t)p * 131072 + (size_t)kh * 32768
                   + (size_t)lane * 16, wB, acc);
        } else {
            dotq_g((const char*)g_h1 + (size_t)p * 131072 + (size_t)(kh - 4) * 32768
                   + (size_t)lane * 16, wB, acc);
        }
        write_partials(cta, lane, kh, acc);   // A-gather done pre-barrier; no extra sync needed
        __syncthreads();
        // ---- B finish ----
        {
            float slo[12], shi[12];
            gather2(cta, fb, fq, slo, shi);
            float z    = sigmoid_f(pick4(slo, fq) + pick4(shi, fq) + bBz);
            float r    = sigmoid_f(pick4(slo + 4, fq) + pick4(shi + 4, fq) + bBr);
            float cand = tanhf(pick4(slo + 8, fq) + bBi + r * (pick4(shi + 8, fq) + bBh));
            float h1n  = z * h1v + (1.f - z) * cand;
            h1v  = m ? h1n : h1v;
            prev = m ? h1n : prev;
            g_h1[(p ^ 1) * 32768 + sidx] = h1v;
            out[((size_t)fb * K_T + t) * K_U + u0g + fq] = prev;
        }
        // no barrier: A(t+1) touches nothing B(t) exchanges before next bar
    }

    // finals: (output, h0f, h1f) in d_out
    const size_t fin = (size_t)K_B * K_T * K_U;
    out[fin + (size_t)fb * K_U + u0g + fq] = h0v;
    out[fin + (size_t)K_B * K_U + (size_t)fb * K_U + u0g + fq] = h1v;
}

// ---------------- launch ----------------
extern "C" void kernel_launch(void* const* d_in, const int* in_sizes, int n_in,
                              void* d_out, int out_size) {
    (void)in_sizes; (void)n_in; (void)out_size;
    const float* x    = (const float*)d_in[0];
    const int*   mask = (const int*)d_in[1];
    const float* W0   = (const float*)d_in[2];
    const float* U0   = (const float*)d_in[3];
    const float* b0   = (const float*)d_in[4];
    const float* W1   = (const float*)d_in[5];
    const float* U1   = (const float*)d_in[6];
    const float* b1   = (const float*)d_in[7];
    float*       out  = (float*)d_out;

    cudaFuncSetAttribute(gru_main, cudaFuncAttributeMaxDynamicSharedMemorySize, SMEM_TOTAL);

    gru_init<<<(2 * K_B * K_U + 255) / 256, 256>>>();
    gru_pack_weights<<<(3 * K_U * 1024 + 255) / 256, 256>>>(W0, U0, W1, U1);
    {
        size_t n4 = (size_t)K_T * 128 * K_B;
        gru_transpose_x<<<(unsigned)((n4 + 255) / 256), 256>>>(x);
    }
    gru_main<<<N_CTA, N_THR, SMEM_TOTAL>>>(mask, b0, b1, out);
}